// round 1
// baseline (speedup 1.0000x reference)
#include <cuda_runtime.h>
#include <cstddef>

#define H_  160
#define W_  160
#define B_  4
#define HW  (H_ * W_)

// ---------------- scratch (device globals: no allocation allowed) ----------
__device__ float g_buf1[(size_t)B_ * 256 * HW];   // 104.9 MB
__device__ float g_buf2[(size_t)B_ * 128 * HW];   //  52.4 MB
__device__ float g_mean[256];
__device__ float g_invstd[256];

// ---------------- main conv: 3x3, stride 1, pad 1, fp32 --------------------
// Block tile: 32 output channels x (8 rows x 32 cols) pixels for one batch.
// Thread: 4 oc x (2x4) pixels = 32 accumulators.
#define TH  8
#define TW  32
#define OCT 32
#define KC  8

__global__ __launch_bounds__(256, 2)
void conv3x3_tiled(const float* __restrict__ X, const float* __restrict__ Wt,
                   float* __restrict__ Y, int Cin, int Cout)
{
    const int tile = blockIdx.x;               // 0..99
    const int tw0  = (tile % (W_ / TW)) * TW;
    const int th0  = (tile / (W_ / TW)) * TH;
    const int oc0  = blockIdx.y * OCT;
    const int b    = blockIdx.z;

    __shared__ float sX[KC][TH + 2][TW + 4];   // row stride 36 floats
    __shared__ float sW[KC][9][OCT];           // [ci][tap][oc] for LDS.128

    const int t     = threadIdx.x;
    const int ocsub = t >> 5;                  // 0..7 (== warp id -> broadcast weights)
    const int p     = t & 31;
    const int r0    = (p >> 3) * 2;            // 0,2,4,6
    const int c0    = (p & 7) * 4;             // 0..28

    float acc[4][2][4];
    #pragma unroll
    for (int a = 0; a < 4; a++)
        #pragma unroll
        for (int r = 0; r < 2; r++)
            #pragma unroll
            for (int c = 0; c < 4; c++) acc[a][r][c] = 0.f;

    const float* Xb = X + (size_t)b * Cin * HW;

    for (int ci0 = 0; ci0 < Cin; ci0 += KC) {
        __syncthreads();
        // ---- load input tile KC x 10 x 34 (zero-padded halo) ----
        for (int e = t; e < KC * 10 * 34; e += 256) {
            int ci  = e / 340;
            int rem = e % 340;
            int r   = rem / 34;
            int c   = rem % 34;
            int gh  = th0 + r - 1;
            int gw  = tw0 + c - 1;
            float v = 0.f;
            if (gh >= 0 && gh < H_ && gw >= 0 && gw < W_)
                v = Xb[(size_t)(ci0 + ci) * HW + gh * W_ + gw];
            sX[ci][r][c] = v;
        }
        // ---- load weight tile (coalesced over tap,ci; scatter into smem) ----
        for (int e = t; e < KC * OCT * 9; e += 256) {
            int tap = e % 9;
            int ci  = (e / 9) % KC;
            int oc  = e / (9 * KC);
            sW[ci][tap][oc] = Wt[((size_t)(oc0 + oc) * Cin + ci0 + ci) * 9 + tap];
        }
        __syncthreads();

        #pragma unroll 1
        for (int ci = 0; ci < KC; ci++) {
            float w[4][9];
            #pragma unroll
            for (int tp = 0; tp < 9; tp++) {
                // 4 consecutive oc -> LDS.128, same address across the warp (broadcast)
                const float4 wv = *(const float4*)&sW[ci][tp][ocsub * 4];
                w[0][tp] = wv.x; w[1][tp] = wv.y; w[2][tp] = wv.z; w[3][tp] = wv.w;
            }
            float xv[4][6];
            #pragma unroll
            for (int rr = 0; rr < 4; rr++) {
                const float4 a = *(const float4*)&sX[ci][r0 + rr][c0];
                xv[rr][0] = a.x; xv[rr][1] = a.y; xv[rr][2] = a.z; xv[rr][3] = a.w;
                xv[rr][4] = sX[ci][r0 + rr][c0 + 4];
                xv[rr][5] = sX[ci][r0 + rr][c0 + 5];
            }
            #pragma unroll
            for (int mr = 0; mr < 4; mr++)
                #pragma unroll
                for (int orow = 0; orow < 2; orow++)
                    #pragma unroll
                    for (int ocol = 0; ocol < 4; ocol++) {
                        float s = acc[mr][orow][ocol];
                        #pragma unroll
                        for (int kh = 0; kh < 3; kh++)
                            #pragma unroll
                            for (int kw = 0; kw < 3; kw++)
                                s += w[mr][kh * 3 + kw] * xv[orow + kh][ocol + kw];
                        acc[mr][orow][ocol] = s;
                    }
        }
    }

    // ---- write out (float4 stores) ----
    #pragma unroll
    for (int mr = 0; mr < 4; mr++) {
        const int oc = oc0 + ocsub * 4 + mr;
        float* Yp = Y + ((size_t)b * Cout + oc) * HW;
        #pragma unroll
        for (int orow = 0; orow < 2; orow++) {
            const int h = th0 + r0 + orow;
            float4 v = make_float4(acc[mr][orow][0], acc[mr][orow][1],
                                   acc[mr][orow][2], acc[mr][orow][3]);
            *(float4*)&Yp[h * W_ + tw0 + c0] = v;
        }
    }
}

// ---------------- per-channel batch stats (train-mode BN) ------------------
__global__ void bn_stats(const float* __restrict__ X, int C)
{
    const int c = blockIdx.x;
    float s = 0.f, s2 = 0.f;
    for (int b = 0; b < B_; b++) {
        const float* q = X + ((size_t)b * C + c) * HW;
        for (int i = threadIdx.x; i < HW; i += 256) {
            float v = q[i];
            s += v; s2 += v * v;
        }
    }
    __shared__ float rs[256], rs2[256];
    rs[threadIdx.x] = s; rs2[threadIdx.x] = s2;
    __syncthreads();
    for (int o = 128; o > 0; o >>= 1) {
        if (threadIdx.x < o) {
            rs[threadIdx.x]  += rs[threadIdx.x + o];
            rs2[threadIdx.x] += rs2[threadIdx.x + o];
        }
        __syncthreads();
    }
    if (threadIdx.x == 0) {
        const float cnt = (float)(B_ * HW);
        float m   = rs[0] / cnt;
        float var = rs2[0] / cnt - m * m;
        g_mean[c]   = m;
        g_invstd[c] = rsqrtf(var + 1e-5f);
    }
}

// ---------------- fused BN apply + ReLU (in place) -------------------------
__global__ void bn_relu(float* __restrict__ X, const float* __restrict__ gamma,
                        const float* __restrict__ beta, int C)
{
    const size_t i = (size_t)blockIdx.x * 256 + threadIdx.x;
    const int c = (int)((i / HW) % C);
    float v = X[i];
    v = (v - g_mean[c]) * g_invstd[c] * gamma[c] + beta[c];
    X[i] = v > 0.f ? v : 0.f;
}

// ---------------- head conv: 3x3 + bias, small Cout -------------------------
#define HTH 16
#define HTW 32

template <int CO>
__global__ __launch_bounds__(256)
void head_conv(const float* __restrict__ X, const float* __restrict__ Wt,
               const float* __restrict__ bias, float* __restrict__ Y, int Cin)
{
    const int tile = blockIdx.x;                 // 0..49
    const int tw0  = (tile % (W_ / HTW)) * HTW;
    const int th0  = (tile / (W_ / HTW)) * HTH;
    const int b    = blockIdx.z;
    const int t    = threadIdx.x;
    const int col  = t & 31;
    const int rp   = (t >> 5) * 2;               // row pair base 0..14

    __shared__ float sX[8][HTH + 2][HTW + 4];
    __shared__ float sW[8][9][CO];

    float acc[2][CO];
    #pragma unroll
    for (int r = 0; r < 2; r++)
        #pragma unroll
        for (int o = 0; o < CO; o++) acc[r][o] = 0.f;

    const float* Xb = X + (size_t)b * Cin * HW;

    for (int ci0 = 0; ci0 < Cin; ci0 += 8) {
        __syncthreads();
        for (int e = t; e < 8 * (HTH + 2) * 34; e += 256) {
            int ci  = e / ((HTH + 2) * 34);
            int rem = e % ((HTH + 2) * 34);
            int r   = rem / 34;
            int c   = rem % 34;
            int gh  = th0 + r - 1;
            int gw  = tw0 + c - 1;
            float v = 0.f;
            if (gh >= 0 && gh < H_ && gw >= 0 && gw < W_)
                v = Xb[(size_t)(ci0 + ci) * HW + gh * W_ + gw];
            sX[ci][r][c] = v;
        }
        for (int e = t; e < 8 * 9 * CO; e += 256) {
            int ci  = e / (9 * CO);
            int rem = e % (9 * CO);
            int tap = rem / CO;
            int oc  = rem % CO;
            sW[ci][tap][oc] = Wt[((size_t)oc * Cin + ci0 + ci) * 9 + tap];
        }
        __syncthreads();

        #pragma unroll 1
        for (int ci = 0; ci < 8; ci++) {
            float xv[4][3];
            #pragma unroll
            for (int rr = 0; rr < 4; rr++)
                #pragma unroll
                for (int cc = 0; cc < 3; cc++)
                    xv[rr][cc] = sX[ci][rp + rr][col + cc];
            #pragma unroll
            for (int oc = 0; oc < CO; oc++) {
                float w[9];
                #pragma unroll
                for (int tp = 0; tp < 9; tp++) w[tp] = sW[ci][tp][oc];
                #pragma unroll
                for (int orow = 0; orow < 2; orow++) {
                    float s = acc[orow][oc];
                    #pragma unroll
                    for (int kh = 0; kh < 3; kh++)
                        #pragma unroll
                        for (int kw = 0; kw < 3; kw++)
                            s += w[kh * 3 + kw] * xv[orow + kh][kw];
                    acc[orow][oc] = s;
                }
            }
        }
    }

    #pragma unroll
    for (int oc = 0; oc < CO; oc++) {
        const float bz = bias[oc];
        #pragma unroll
        for (int orow = 0; orow < 2; orow++) {
            const int h = th0 + rp + orow;
            Y[((size_t)b * CO + oc) * HW + h * W_ + tw0 + col] = acc[orow][oc] + bz;
        }
    }
}

// ---------------- launcher ---------------------------------------------------
static void run_branch(const float* fpn,
                       const float* w1, const float* g1, const float* b1,
                       const float* w2, const float* g2, const float* b2,
                       float* buf1, float* buf2)
{
    dim3 cg1(100, 256 / OCT, B_);
    dim3 cg2(100, 128 / OCT, B_);
    conv3x3_tiled<<<cg1, 256>>>(fpn, w1, buf1, 256, 256);
    bn_stats<<<256, 256>>>(buf1, 256);
    bn_relu<<<(unsigned)((size_t)B_ * 256 * HW / 256), 256>>>(buf1, g1, b1, 256);
    conv3x3_tiled<<<cg2, 256>>>(buf1, w2, buf2, 256, 128);
    bn_stats<<<128, 256>>>(buf2, 128);
    bn_relu<<<(unsigned)((size_t)B_ * 128 * HW / 256), 256>>>(buf2, g2, b2, 128);
}

extern "C" void kernel_launch(void* const* d_in, const int* in_sizes, int n_in,
                              void* d_out, int out_size)
{
    const float* fpn        = (const float*)d_in[0];
    const float* w_sc1      = (const float*)d_in[1];
    const float* g_sc1      = (const float*)d_in[2];
    const float* b_sc1      = (const float*)d_in[3];
    const float* w_sc2      = (const float*)d_in[4];
    const float* g_sc2      = (const float*)d_in[5];
    const float* b_sc2      = (const float*)d_in[6];
    const float* w_shrink   = (const float*)d_in[7];
    const float* bias_shrink= (const float*)d_in[8];
    const float* w_cent     = (const float*)d_in[9];
    const float* bias_cent  = (const float*)d_in[10];
    const float* w_p1       = (const float*)d_in[11];
    const float* g_p1       = (const float*)d_in[12];
    const float* b_p1       = (const float*)d_in[13];
    const float* w_p2       = (const float*)d_in[14];
    const float* g_p2       = (const float*)d_in[15];
    const float* b_p2       = (const float*)d_in[16];
    const float* w_p3       = (const float*)d_in[17];
    const float* bias_p3    = (const float*)d_in[18];
    const float* w_s1       = (const float*)d_in[19];
    const float* g_s1       = (const float*)d_in[20];
    const float* b_s1       = (const float*)d_in[21];
    const float* w_s2       = (const float*)d_in[22];
    const float* g_s2       = (const float*)d_in[23];
    const float* b_s2       = (const float*)d_in[24];
    const float* w_s3       = (const float*)d_in[25];
    const float* bias_s3    = (const float*)d_in[26];

    float* out = (float*)d_out;

    float *buf1 = nullptr, *buf2 = nullptr;
    cudaGetSymbolAddress((void**)&buf1, g_buf1);
    cudaGetSymbolAddress((void**)&buf2, g_buf2);

    dim3 hgrid(50, 1, B_);
    const size_t seg = (size_t)B_ * HW;   // 102400

    // sc branch -> shrink, centroid
    run_branch(fpn, w_sc1, g_sc1, b_sc1, w_sc2, g_sc2, b_sc2, buf1, buf2);
    head_conv<1><<<hgrid, 256>>>(buf2, w_shrink, bias_shrink, out + 0,       128);
    head_conv<1><<<hgrid, 256>>>(buf2, w_cent,   bias_cent,   out + seg,     128);

    // param branch -> param (2 ch)
    run_branch(fpn, w_p1, g_p1, b_p1, w_p2, g_p2, b_p2, buf1, buf2);
    head_conv<2><<<hgrid, 256>>>(buf2, w_p3, bias_p3, out + 2 * seg, 128);

    // shift branch -> shift (8 ch)
    run_branch(fpn, w_s1, g_s1, b_s1, w_s2, g_s2, b_s2, buf1, buf2);
    head_conv<8><<<hgrid, 256>>>(buf2, w_s3, bias_s3, out + 4 * seg, 128);
}